// round 14
// baseline (speedup 1.0000x reference)
#include <cuda_runtime.h>
#include <cstdint>

#define B_   256
#define T_   512
#define DIN  128
#define H_   512
#define DOUT 64
#define KB   4       // k-rows per register block
#define NBLK 32      // blocks per k-quarter (128 k)

// Scratch (allocation-free rule: __device__ globals)
__device__ float g_xproj[(size_t)B_ * T_ * H_];  // [b][t][h] = inputs@Win + brec
__device__ float g_hall [(size_t)B_ * T_ * H_];  // [b][t][h] = h_t for all t

// Packed fp32x2 FMA
union F2U { float2 f; unsigned long long u; };
__device__ __forceinline__ float2 ffma2(float2 a, float2 b, float2 c) {
    F2U A, Bv, C, D;
    A.f = a; Bv.f = b; C.f = c;
    asm("fma.rn.f32x2 %0, %1, %2, %3;" : "=l"(D.u) : "l"(A.u), "l"(Bv.u), "l"(C.u));
    return D.f;
}

// ---------------------------------------------------------------------------
// Kernel A: xproj = inputs @ Win + brec   (measured 579us)
// ---------------------------------------------------------------------------
__global__ void __launch_bounds__(256) rnn_xproj(
    const float* __restrict__ inputs,
    const float* __restrict__ Win,
    const float* __restrict__ brec)
{
    __shared__ __align__(16) float2 x_dup[16][DIN];
    const int tid = threadIdx.x;
    const size_t r0 = (size_t)blockIdx.x * 16;

    for (int i = tid; i < 16 * DIN; i += 256) {
        int r = i >> 7, k = i & (DIN - 1);
        float v = inputs[(r0 + r) * DIN + k];
        x_dup[r][k] = make_float2(v, v);
    }
    __syncthreads();

    const float2* __restrict__ W2 = reinterpret_cast<const float2*>(Win);
    float2 acc[16];
#pragma unroll
    for (int r = 0; r < 16; r++) acc[r] = make_float2(0.f, 0.f);

#pragma unroll 2
    for (int k = 0; k < DIN; k += 2) {
        float2 w0 = W2[(size_t)k * (H_ / 2) + tid];
        float2 w1 = W2[(size_t)(k + 1) * (H_ / 2) + tid];
#pragma unroll
        for (int r = 0; r < 16; r++) {
            float4 hx = *reinterpret_cast<const float4*>(&x_dup[r][k]);
            acc[r] = ffma2(make_float2(hx.x, hx.y), w0, acc[r]);
            acc[r] = ffma2(make_float2(hx.z, hx.w), w1, acc[r]);
        }
    }

    float2 bb = reinterpret_cast<const float2*>(brec)[tid];
    float2* __restrict__ out2 = reinterpret_cast<float2*>(g_xproj);
#pragma unroll
    for (int r = 0; r < 16; r++)
        out2[(r0 + r) * (H_ / 2) + tid] = make_float2(acc[r].x + bb.x, acc[r].y + bb.y);
}

// ---------------------------------------------------------------------------
// Kernel B: recurrence. 64 CTAs x 4 batch rows x 256 threads. Sync-free W
// streaming (LDG.128 double-buffered). 4-way k-split; each thread owns TWO
// CONTIGUOUS col groups [4q,4q+4) and [256+4q,256+4q+4), so every warp
// LDG.128 row-span is a fully-used 512B (W wavefronts stay at 8192/step)
// while h-broadcast LDS is HALVED vs R8 (2048 wavefronts/step). Thread:
// p = tid>>6 (k-quarter), q = tid&63. Step end: 4-way SMEM reduction;
// thread finalizes batch p, BOTH its col groups. 64KB smem total.
// Exactly 2 __syncthreads per step; zero cross-CTA sync.
// ---------------------------------------------------------------------------
extern __shared__ __align__(16) unsigned char smraw[];

__global__ void __launch_bounds__(256, 1)
rnn_recurrent(const float* __restrict__ Wrec,
              const float* __restrict__ h0)
{
    float2* hdup = reinterpret_cast<float2*>(smraw);            // [2][4][512] {h,h} 32KB
    float4* red  = reinterpret_cast<float4*>(smraw + 32768);    // [4][4][64][2]     32KB

    const int tid = threadIdx.x;
    const int p   = tid >> 6;          // k-quarter 0..3 == batch finalized
    const int q   = tid & 63;
    const int cA  = 4 * q;             // col group A base (group B at +256)
    const int k0  = 128 * p;
    const int b0  = blockIdx.x * 4;

    for (int i = tid; i < 4 * H_; i += 256) {   // h = h0 for all 4 rows (dup)
        int b = i >> 9, k = i & 511;
        float v = h0[k];
        hdup[(size_t)b * H_ + k] = make_float2(v, v);
    }
    __syncthreads();

    // W: per k-row two LDG.128 at cols cA and 256+cA (each warp-contiguous).
    const char* wptr = reinterpret_cast<const char*>(Wrec + (size_t)k0 * H_ + cA);
    const size_t ROWB = H_ * 4;        // 2KB per k-row
    const size_t GRPB = 256 * 4;       // 1KB between col groups
    float4 wb0[2 * KB], wb1[2 * KB];   // [row][groupA/groupB]

#pragma unroll
    for (int r = 0; r < KB; r++) {     // prologue: block 0
        wb0[2*r]   = __ldg(reinterpret_cast<const float4*>(wptr + (size_t)r * ROWB));
        wb0[2*r+1] = __ldg(reinterpret_cast<const float4*>(wptr + (size_t)r * ROWB + GRPB));
    }

    float4 xpA = *reinterpret_cast<const float4*>(
        g_xproj + ((size_t)(b0 + p) * T_) * H_ + cA);
    float4 xpB = *reinterpret_cast<const float4*>(
        g_xproj + ((size_t)(b0 + p) * T_) * H_ + cA + 256);

    float2 acc[4][4];                  // [batch][A0,A1,B0,B1]
#pragma unroll
    for (int b = 0; b < 4; b++)
#pragma unroll
        for (int c = 0; c < 4; c++) acc[b][c] = make_float2(0.f, 0.f);

    int hb = 0;
    for (int t = 0; t < T_; t++) {
        const float2* hbuf = hdup + (size_t)hb * 4 * H_;
#pragma unroll 1
        for (int bb = 0; bb < NBLK / 2; bb++) {
            const int blk0 = 2 * bb, blk1 = 2 * bb + 1;

            // prefetch blk1 -> wb1, compute blk0 from wb0
            {
                const char* pf = wptr + (size_t)blk1 * (KB * ROWB);
#pragma unroll
                for (int r = 0; r < KB; r++) {
                    wb1[2*r]   = __ldg(reinterpret_cast<const float4*>(pf + (size_t)r * ROWB));
                    wb1[2*r+1] = __ldg(reinterpret_cast<const float4*>(pf + (size_t)r * ROWB + GRPB));
                }
            }
            {
                const int kb = k0 + blk0 * KB;
#pragma unroll
                for (int r = 0; r < KB; r += 2) {
                    float4 w0a = wb0[2*r],   w0b = wb0[2*r+1];     // row r   (A,B)
                    float4 w1a = wb0[2*r+2], w1b = wb0[2*r+3];     // row r+1 (A,B)
#pragma unroll
                    for (int b = 0; b < 4; b++) {
                        float4 hh = *reinterpret_cast<const float4*>(
                            &hbuf[(size_t)b * H_ + kb + r]);       // {hk,hk,hk1,hk1}
                        float2 hx = make_float2(hh.x, hh.y), hz = make_float2(hh.z, hh.w);
                        acc[b][0] = ffma2(hx, make_float2(w0a.x, w0a.y), acc[b][0]);
                        acc[b][1] = ffma2(hx, make_float2(w0a.z, w0a.w), acc[b][1]);
                        acc[b][2] = ffma2(hx, make_float2(w0b.x, w0b.y), acc[b][2]);
                        acc[b][3] = ffma2(hx, make_float2(w0b.z, w0b.w), acc[b][3]);
                        acc[b][0] = ffma2(hz, make_float2(w1a.x, w1a.y), acc[b][0]);
                        acc[b][1] = ffma2(hz, make_float2(w1a.z, w1a.w), acc[b][1]);
                        acc[b][2] = ffma2(hz, make_float2(w1b.x, w1b.y), acc[b][2]);
                        acc[b][3] = ffma2(hz, make_float2(w1b.z, w1b.w), acc[b][3]);
                    }
                }
            }

            // prefetch next-next block (wraps to 0) -> wb0, compute blk1 from wb1
            {
                const int nblk = (blk1 + 1) & (NBLK - 1);
                const char* pf = wptr + (size_t)nblk * (KB * ROWB);
#pragma unroll
                for (int r = 0; r < KB; r++) {
                    wb0[2*r]   = __ldg(reinterpret_cast<const float4*>(pf + (size_t)r * ROWB));
                    wb0[2*r+1] = __ldg(reinterpret_cast<const float4*>(pf + (size_t)r * ROWB + GRPB));
                }
            }
            {
                const int kb = k0 + blk1 * KB;
#pragma unroll
                for (int r = 0; r < KB; r += 2) {
                    float4 w0a = wb1[2*r],   w0b = wb1[2*r+1];
                    float4 w1a = wb1[2*r+2], w1b = wb1[2*r+3];
#pragma unroll
                    for (int b = 0; b < 4; b++) {
                        float4 hh = *reinterpret_cast<const float4*>(
                            &hbuf[(size_t)b * H_ + kb + r]);
                        float2 hx = make_float2(hh.x, hh.y), hz = make_float2(hh.z, hh.w);
                        acc[b][0] = ffma2(hx, make_float2(w0a.x, w0a.y), acc[b][0]);
                        acc[b][1] = ffma2(hx, make_float2(w0a.z, w0a.w), acc[b][1]);
                        acc[b][2] = ffma2(hx, make_float2(w0b.x, w0b.y), acc[b][2]);
                        acc[b][3] = ffma2(hx, make_float2(w0b.z, w0b.w), acc[b][3]);
                        acc[b][0] = ffma2(hz, make_float2(w1a.x, w1a.y), acc[b][0]);
                        acc[b][1] = ffma2(hz, make_float2(w1a.z, w1a.w), acc[b][1]);
                        acc[b][2] = ffma2(hz, make_float2(w1b.x, w1b.y), acc[b][2]);
                        acc[b][3] = ffma2(hz, make_float2(w1b.z, w1b.w), acc[b][3]);
                    }
                }
            }
        }

        // ---- step end: 4-way cross-k reduction ----
        // red[b][p][q][grp]. Publish only partner batches (b != p); own
        // batch-p partials stay in registers.
#pragma unroll
        for (int b = 0; b < 4; b++) {
            if (b != p) {
                size_t base = (((size_t)b * 4 + p) * 64 + q) * 2;
                red[base]     = make_float4(acc[b][0].x, acc[b][0].y, acc[b][1].x, acc[b][1].y);
                red[base + 1] = make_float4(acc[b][2].x, acc[b][2].y, acc[b][3].x, acc[b][3].y);
            }
        }
        __syncthreads();

        float4 sA = make_float4(acc[p][0].x, acc[p][0].y, acc[p][1].x, acc[p][1].y);
        float4 sB = make_float4(acc[p][2].x, acc[p][2].y, acc[p][3].x, acc[p][3].y);
#pragma unroll
        for (int d = 1; d < 4; d++) {
            int pp = (p + d) & 3;
            size_t base = (((size_t)p * 4 + pp) * 64 + q) * 2;
            float4 rA = red[base], rB = red[base + 1];
            sA.x += rA.x; sA.y += rA.y; sA.z += rA.z; sA.w += rA.w;
            sB.x += rB.x; sB.y += rB.y; sB.z += rB.z; sB.w += rB.w;
        }
        float a0 = tanhf(sA.x + xpA.x);
        float a1 = tanhf(sA.y + xpA.y);
        float a2 = tanhf(sA.z + xpA.z);
        float a3 = tanhf(sA.w + xpA.w);
        float e0 = tanhf(sB.x + xpB.x);
        float e1 = tanhf(sB.y + xpB.y);
        float e2 = tanhf(sB.z + xpB.z);
        float e3 = tanhf(sB.w + xpB.w);

        float* hrow = g_hall + ((size_t)(b0 + p) * T_ + t) * H_;
        *reinterpret_cast<float4*>(hrow + cA)       = make_float4(a0, a1, a2, a3);
        *reinterpret_cast<float4*>(hrow + cA + 256) = make_float4(e0, e1, e2, e3);

        float2* hnew = hdup + (size_t)(hb ^ 1) * 4 * H_ + (size_t)p * H_;
        float4* hdA = reinterpret_cast<float4*>(hnew + cA);
        hdA[0] = make_float4(a0, a0, a1, a1);
        hdA[1] = make_float4(a2, a2, a3, a3);
        float4* hdB = reinterpret_cast<float4*>(hnew + cA + 256);
        hdB[0] = make_float4(e0, e0, e1, e1);
        hdB[1] = make_float4(e2, e2, e3, e3);

#pragma unroll
        for (int b = 0; b < 4; b++)
#pragma unroll
            for (int c = 0; c < 4; c++) acc[b][c] = make_float2(0.f, 0.f);
        if (t + 1 < T_) {                             // overlaps tail, not GEMM head
            const float* xrow = g_xproj + ((size_t)(b0 + p) * T_ + (t + 1)) * H_;
            xpA = *reinterpret_cast<const float4*>(xrow + cA);
            xpB = *reinterpret_cast<const float4*>(xrow + cA + 256);
        }
        __syncthreads();
        hb ^= 1;
    }
}

// ---------------------------------------------------------------------------
// Kernel C: out = g_hall @ Wout + bout
// ---------------------------------------------------------------------------
__global__ void __launch_bounds__(256, 1) rnn_outproj(
    const float* __restrict__ Wout,
    const float* __restrict__ bout,
    float* __restrict__ out)
{
    __shared__ __align__(16) float2 hdq[64][64];
    const int tid = threadIdx.x;
    const int pair = tid & 31;
    const int rg = tid >> 5;
    const size_t r0 = (size_t)blockIdx.x * 64;

    float2 acc[8];
#pragma unroll
    for (int i = 0; i < 8; i++) acc[i] = make_float2(0.f, 0.f);

    const float2* __restrict__ Wo2 = reinterpret_cast<const float2*>(Wout);

    for (int kc = 0; kc < H_; kc += 64) {
        __syncthreads();
        for (int i = tid; i < 64 * 64; i += 256) {
            int r = i >> 6, k = i & 63;
            float v = g_hall[(r0 + r) * H_ + kc + k];
            hdq[r][k] = make_float2(v, v);
        }
        __syncthreads();

#pragma unroll 4
        for (int kk = 0; kk < 64; kk += 2) {
            float2 w0 = Wo2[(size_t)(kc + kk) * (DOUT / 2) + pair];
            float2 w1 = Wo2[(size_t)(kc + kk + 1) * (DOUT / 2) + pair];
#pragma unroll
            for (int i = 0; i < 8; i++) {
                int r = rg * 8 + i;
                float4 hx = *reinterpret_cast<const float4*>(&hdq[r][kk]);
                acc[i] = ffma2(make_float2(hx.x, hx.y), w0, acc[i]);
                acc[i] = ffma2(make_float2(hx.z, hx.w), w1, acc[i]);
            }
        }
    }

    float2 bb = reinterpret_cast<const float2*>(bout)[pair];
    float2* __restrict__ out2 = reinterpret_cast<float2*>(out);
#pragma unroll
    for (int i = 0; i < 8; i++) {
        int r = rg * 8 + i;
        out2[(r0 + r) * (DOUT / 2) + pair] =
            make_float2(acc[i].x + bb.x, acc[i].y + bb.y);
    }
}

// ---------------------------------------------------------------------------
extern "C" void kernel_launch(void* const* d_in, const int* in_sizes, int n_in,
                              void* d_out, int out_size)
{
    const float* inputs = (const float*)d_in[0];
    const float* Win    = (const float*)d_in[1];
    const float* Wrec   = (const float*)d_in[2];
    const float* brec   = (const float*)d_in[3];
    const float* Wout   = (const float*)d_in[4];
    const float* bout   = (const float*)d_in[5];
    const float* h0     = (const float*)d_in[6];

    cudaFuncSetAttribute(rnn_recurrent,
                         cudaFuncAttributeMaxDynamicSharedMemorySize, 65536);

    rnn_xproj<<<(B_ * T_) / 16, 256>>>(inputs, Win, brec);
    rnn_recurrent<<<B_ / 4, 256, 65536>>>(Wrec, h0);
    rnn_outproj<<<(B_ * T_) / 64, 256>>>(Wout, bout, (float*)d_out);
}

// round 15
// speedup vs baseline: 1.2889x; 1.2889x over previous
#include <cuda_runtime.h>
#include <cstdint>

#define B_   256
#define T_   512
#define DIN  128
#define H_   512
#define DOUT 64
#define KB   8       // k-rows per register block (>=8: covers L2 latency)
#define NBLK 16      // blocks per k-quarter (128 k)

// Scratch (allocation-free rule: __device__ globals)
__device__ float g_xproj[(size_t)B_ * T_ * H_];  // [b][t][h] = inputs@Win + brec
__device__ float g_hall [(size_t)B_ * T_ * H_];  // [b][t][h] = h_t for all t

// Packed fp32x2 FMA
union F2U { float2 f; unsigned long long u; };
__device__ __forceinline__ float2 ffma2(float2 a, float2 b, float2 c) {
    F2U A, Bv, C, D;
    A.f = a; Bv.f = b; C.f = c;
    asm("fma.rn.f32x2 %0, %1, %2, %3;" : "=l"(D.u) : "l"(A.u), "l"(Bv.u), "l"(C.u));
    return D.f;
}

// ---------------------------------------------------------------------------
// Kernel A: xproj = inputs @ Win + brec   (measured 579us)
// ---------------------------------------------------------------------------
__global__ void __launch_bounds__(256) rnn_xproj(
    const float* __restrict__ inputs,
    const float* __restrict__ Win,
    const float* __restrict__ brec)
{
    __shared__ __align__(16) float2 x_dup[16][DIN];
    const int tid = threadIdx.x;
    const size_t r0 = (size_t)blockIdx.x * 16;

    for (int i = tid; i < 16 * DIN; i += 256) {
        int r = i >> 7, k = i & (DIN - 1);
        float v = inputs[(r0 + r) * DIN + k];
        x_dup[r][k] = make_float2(v, v);
    }
    __syncthreads();

    const float2* __restrict__ W2 = reinterpret_cast<const float2*>(Win);
    float2 acc[16];
#pragma unroll
    for (int r = 0; r < 16; r++) acc[r] = make_float2(0.f, 0.f);

#pragma unroll 2
    for (int k = 0; k < DIN; k += 2) {
        float2 w0 = W2[(size_t)k * (H_ / 2) + tid];
        float2 w1 = W2[(size_t)(k + 1) * (H_ / 2) + tid];
#pragma unroll
        for (int r = 0; r < 16; r++) {
            float4 hx = *reinterpret_cast<const float4*>(&x_dup[r][k]);
            acc[r] = ffma2(make_float2(hx.x, hx.y), w0, acc[r]);
            acc[r] = ffma2(make_float2(hx.z, hx.w), w1, acc[r]);
        }
    }

    float2 bb = reinterpret_cast<const float2*>(brec)[tid];
    float2* __restrict__ out2 = reinterpret_cast<float2*>(g_xproj);
#pragma unroll
    for (int r = 0; r < 16; r++)
        out2[(r0 + r) * (H_ / 2) + tid] = make_float2(acc[r].x + bb.x, acc[r].y + bb.y);
}

// ---------------------------------------------------------------------------
// Kernel B: recurrence. 64 CTAs x 4 batch rows x 256 threads. Sync-free W
// streaming, LDG.128 double-buffered with KB=8 rows/buffer (16 loads in
// flight -> L2 latency covered; KB=4 in R13 exposed ~100-150cyc per block).
// 4-way k-split; thread owns TWO CONTIGUOUS col groups [4q,4q+4) and
// [256+4q,+4) (warp row-span fully-used 512B). h-broadcast LDS halved vs
// R8. Thread: p = tid>>6 (k-quarter), q = tid&63. Step end: 4-way SMEM
// reduction; thread finalizes batch p, both groups. 64KB smem.
// Exactly 2 __syncthreads per step; zero cross-CTA sync.
// ---------------------------------------------------------------------------
extern __shared__ __align__(16) unsigned char smraw[];

__global__ void __launch_bounds__(256, 1)
rnn_recurrent(const float* __restrict__ Wrec,
              const float* __restrict__ h0)
{
    float2* hdup = reinterpret_cast<float2*>(smraw);            // [2][4][512] {h,h} 32KB
    float4* red  = reinterpret_cast<float4*>(smraw + 32768);    // [4][4][64][2]     32KB

    const int tid = threadIdx.x;
    const int p   = tid >> 6;          // k-quarter 0..3 == batch finalized
    const int q   = tid & 63;
    const int cA  = 4 * q;             // col group A base (group B at +256)
    const int k0  = 128 * p;
    const int b0  = blockIdx.x * 4;

    for (int i = tid; i < 4 * H_; i += 256) {   // h = h0 for all 4 rows (dup)
        int b = i >> 9, k = i & 511;
        float v = h0[k];
        hdup[(size_t)b * H_ + k] = make_float2(v, v);
    }
    __syncthreads();

    // W: per k-row two LDG.128 at cols cA and 256+cA (each warp-contiguous).
    const char* wptr = reinterpret_cast<const char*>(Wrec + (size_t)k0 * H_ + cA);
    const size_t ROWB = H_ * 4;        // 2KB per k-row
    const size_t GRPB = 256 * 4;       // 1KB between col groups
    float4 wb0[2 * KB], wb1[2 * KB];   // [row][groupA/groupB]

#pragma unroll
    for (int r = 0; r < KB; r++) {     // prologue: block 0
        wb0[2*r]   = __ldg(reinterpret_cast<const float4*>(wptr + (size_t)r * ROWB));
        wb0[2*r+1] = __ldg(reinterpret_cast<const float4*>(wptr + (size_t)r * ROWB + GRPB));
    }

    float4 xpA = *reinterpret_cast<const float4*>(
        g_xproj + ((size_t)(b0 + p) * T_) * H_ + cA);
    float4 xpB = *reinterpret_cast<const float4*>(
        g_xproj + ((size_t)(b0 + p) * T_) * H_ + cA + 256);

    float2 acc[4][4];                  // [batch][A0,A1,B0,B1]
#pragma unroll
    for (int b = 0; b < 4; b++)
#pragma unroll
        for (int c = 0; c < 4; c++) acc[b][c] = make_float2(0.f, 0.f);

    int hb = 0;
    for (int t = 0; t < T_; t++) {
        const float2* hbuf = hdup + (size_t)hb * 4 * H_;
#pragma unroll 1
        for (int bb = 0; bb < NBLK / 2; bb++) {
            const int blk0 = 2 * bb, blk1 = 2 * bb + 1;

            // prefetch blk1 -> wb1, compute blk0 from wb0
            {
                const char* pf = wptr + (size_t)blk1 * (KB * ROWB);
#pragma unroll
                for (int r = 0; r < KB; r++) {
                    wb1[2*r]   = __ldg(reinterpret_cast<const float4*>(pf + (size_t)r * ROWB));
                    wb1[2*r+1] = __ldg(reinterpret_cast<const float4*>(pf + (size_t)r * ROWB + GRPB));
                }
            }
            {
                const int kb = k0 + blk0 * KB;
#pragma unroll
                for (int r = 0; r < KB; r += 2) {
                    float4 w0a = wb0[2*r],   w0b = wb0[2*r+1];     // row r   (A,B)
                    float4 w1a = wb0[2*r+2], w1b = wb0[2*r+3];     // row r+1 (A,B)
#pragma unroll
                    for (int b = 0; b < 4; b++) {
                        float4 hh = *reinterpret_cast<const float4*>(
                            &hbuf[(size_t)b * H_ + kb + r]);       // {hk,hk,hk1,hk1}
                        float2 hx = make_float2(hh.x, hh.y), hz = make_float2(hh.z, hh.w);
                        acc[b][0] = ffma2(hx, make_float2(w0a.x, w0a.y), acc[b][0]);
                        acc[b][1] = ffma2(hx, make_float2(w0a.z, w0a.w), acc[b][1]);
                        acc[b][2] = ffma2(hx, make_float2(w0b.x, w0b.y), acc[b][2]);
                        acc[b][3] = ffma2(hx, make_float2(w0b.z, w0b.w), acc[b][3]);
                        acc[b][0] = ffma2(hz, make_float2(w1a.x, w1a.y), acc[b][0]);
                        acc[b][1] = ffma2(hz, make_float2(w1a.z, w1a.w), acc[b][1]);
                        acc[b][2] = ffma2(hz, make_float2(w1b.x, w1b.y), acc[b][2]);
                        acc[b][3] = ffma2(hz, make_float2(w1b.z, w1b.w), acc[b][3]);
                    }
                }
            }

            // prefetch next-next block (wraps to 0) -> wb0, compute blk1 from wb1
            {
                const int nblk = (blk1 + 1) & (NBLK - 1);
                const char* pf = wptr + (size_t)nblk * (KB * ROWB);
#pragma unroll
                for (int r = 0; r < KB; r++) {
                    wb0[2*r]   = __ldg(reinterpret_cast<const float4*>(pf + (size_t)r * ROWB));
                    wb0[2*r+1] = __ldg(reinterpret_cast<const float4*>(pf + (size_t)r * ROWB + GRPB));
                }
            }
            {
                const int kb = k0 + blk1 * KB;
#pragma unroll
                for (int r = 0; r < KB; r += 2) {
                    float4 w0a = wb1[2*r],   w0b = wb1[2*r+1];
                    float4 w1a = wb1[2*r+2], w1b = wb1[2*r+3];
#pragma unroll
                    for (int b = 0; b < 4; b++) {
                        float4 hh = *reinterpret_cast<const float4*>(
                            &hbuf[(size_t)b * H_ + kb + r]);
                        float2 hx = make_float2(hh.x, hh.y), hz = make_float2(hh.z, hh.w);
                        acc[b][0] = ffma2(hx, make_float2(w0a.x, w0a.y), acc[b][0]);
                        acc[b][1] = ffma2(hx, make_float2(w0a.z, w0a.w), acc[b][1]);
                        acc[b][2] = ffma2(hx, make_float2(w0b.x, w0b.y), acc[b][2]);
                        acc[b][3] = ffma2(hx, make_float2(w0b.z, w0b.w), acc[b][3]);
                        acc[b][0] = ffma2(hz, make_float2(w1a.x, w1a.y), acc[b][0]);
                        acc[b][1] = ffma2(hz, make_float2(w1a.z, w1a.w), acc[b][1]);
                        acc[b][2] = ffma2(hz, make_float2(w1b.x, w1b.y), acc[b][2]);
                        acc[b][3] = ffma2(hz, make_float2(w1b.z, w1b.w), acc[b][3]);
                    }
                }
            }
        }

        // ---- step end: 4-way cross-k reduction ----
        // red[b][p][q][grp]. Publish only partner batches (b != p); own
        // batch-p partials stay in registers.
#pragma unroll
        for (int b = 0; b < 4; b++) {
            if (b != p) {
                size_t base = (((size_t)b * 4 + p) * 64 + q) * 2;
                red[base]     = make_float4(acc[b][0].x, acc[b][0].y, acc[b][1].x, acc[b][1].y);
                red[base + 1] = make_float4(acc[b][2].x, acc[b][2].y, acc[b][3].x, acc[b][3].y);
            }
        }
        __syncthreads();

        float4 sA = make_float4(acc[p][0].x, acc[p][0].y, acc[p][1].x, acc[p][1].y);
        float4 sB = make_float4(acc[p][2].x, acc[p][2].y, acc[p][3].x, acc[p][3].y);
#pragma unroll
        for (int d = 1; d < 4; d++) {
            int pp = (p + d) & 3;
            size_t base = (((size_t)p * 4 + pp) * 64 + q) * 2;
            float4 rA = red[base], rB = red[base + 1];
            sA.x += rA.x; sA.y += rA.y; sA.z += rA.z; sA.w += rA.w;
            sB.x += rB.x; sB.y += rB.y; sB.z += rB.z; sB.w += rB.w;
        }
        float a0 = tanhf(sA.x + xpA.x);
        float a1 = tanhf(sA.y + xpA.y);
        float a2 = tanhf(sA.z + xpA.z);
        float a3 = tanhf(sA.w + xpA.w);
        float e0 = tanhf(sB.x + xpB.x);
        float e1 = tanhf(sB.y + xpB.y);
        float e2 = tanhf(sB.z + xpB.z);
        float e3 = tanhf(sB.w + xpB.w);

        float* hrow = g_hall + ((size_t)(b0 + p) * T_ + t) * H_;
        *reinterpret_cast<float4*>(hrow + cA)       = make_float4(a0, a1, a2, a3);
        *reinterpret_cast<float4*>(hrow + cA + 256) = make_float4(e0, e1, e2, e3);

        float2* hnew = hdup + (size_t)(hb ^ 1) * 4 * H_ + (size_t)p * H_;
        float4* hdA = reinterpret_cast<float4*>(hnew + cA);
        hdA[0] = make_float4(a0, a0, a1, a1);
        hdA[1] = make_float4(a2, a2, a3, a3);
        float4* hdB = reinterpret_cast<float4*>(hnew + cA + 256);
        hdB[0] = make_float4(e0, e0, e1, e1);
        hdB[1] = make_float4(e2, e2, e3, e3);

#pragma unroll
        for (int b = 0; b < 4; b++)
#pragma unroll
            for (int c = 0; c < 4; c++) acc[b][c] = make_float2(0.f, 0.f);
        if (t + 1 < T_) {                             // overlaps tail, not GEMM head
            const float* xrow = g_xproj + ((size_t)(b0 + p) * T_ + (t + 1)) * H_;
            xpA = *reinterpret_cast<const float4*>(xrow + cA);
            xpB = *reinterpret_cast<const float4*>(xrow + cA + 256);
        }
        __syncthreads();
        hb ^= 1;
    }
}

// ---------------------------------------------------------------------------
// Kernel C: out = g_hall @ Wout + bout
// ---------------------------------------------------------------------------
__global__ void __launch_bounds__(256, 1) rnn_outproj(
    const float* __restrict__ Wout,
    const float* __restrict__ bout,
    float* __restrict__ out)
{
    __shared__ __align__(16) float2 hdq[64][64];
    const int tid = threadIdx.x;
    const int pair = tid & 31;
    const int rg = tid >> 5;
    const size_t r0 = (size_t)blockIdx.x * 64;

    float2 acc[8];
#pragma unroll
    for (int i = 0; i < 8; i++) acc[i] = make_float2(0.f, 0.f);

    const float2* __restrict__ Wo2 = reinterpret_cast<const float2*>(Wout);

    for (int kc = 0; kc < H_; kc += 64) {
        __syncthreads();
        for (int i = tid; i < 64 * 64; i += 256) {
            int r = i >> 6, k = i & 63;
            float v = g_hall[(r0 + r) * H_ + kc + k];
            hdq[r][k] = make_float2(v, v);
        }
        __syncthreads();

#pragma unroll 4
        for (int kk = 0; kk < 64; kk += 2) {
            float2 w0 = Wo2[(size_t)(kc + kk) * (DOUT / 2) + pair];
            float2 w1 = Wo2[(size_t)(kc + kk + 1) * (DOUT / 2) + pair];
#pragma unroll
            for (int i = 0; i < 8; i++) {
                int r = rg * 8 + i;
                float4 hx = *reinterpret_cast<const float4*>(&hdq[r][kk]);
                acc[i] = ffma2(make_float2(hx.x, hx.y), w0, acc[i]);
                acc[i] = ffma2(make_float2(hx.z, hx.w), w1, acc[i]);
            }
        }
    }

    float2 bb = reinterpret_cast<const float2*>(bout)[pair];
    float2* __restrict__ out2 = reinterpret_cast<float2*>(out);
#pragma unroll
    for (int i = 0; i < 8; i++) {
        int r = rg * 8 + i;
        out2[(r0 + r) * (DOUT / 2) + pair] =
            make_float2(acc[i].x + bb.x, acc[i].y + bb.y);
    }
}

// ---------------------------------------------------------------------------
extern "C" void kernel_launch(void* const* d_in, const int* in_sizes, int n_in,
                              void* d_out, int out_size)
{
    const float* inputs = (const float*)d_in[0];
    const float* Win    = (const float*)d_in[1];
    const float* Wrec   = (const float*)d_in[2];
    const float* brec   = (const float*)d_in[3];
    const float* Wout   = (const float*)d_in[4];
    const float* bout   = (const float*)d_in[5];
    const float* h0     = (const float*)d_in[6];

    cudaFuncSetAttribute(rnn_recurrent,
                         cudaFuncAttributeMaxDynamicSharedMemorySize, 65536);

    rnn_xproj<<<(B_ * T_) / 16, 256>>>(inputs, Win, brec);
    rnn_recurrent<<<B_ / 4, 256, 65536>>>(Wrec, h0);
    rnn_outproj<<<(B_ * T_) / 64, 256>>>(Wout, bout, (float*)d_out);
}